// round 13
// baseline (speedup 1.0000x reference)
#include <cuda_runtime.h>
#include <cuda_bf16.h>
#include <cstdint>

#define B_ 4
#define C_ 256
#define H_ 128
#define W_ 128
#define HW_ (H_*W_)
#define HEADS_ 8
#define PW_ 130
#define PP_ (PW_*PW_)

// ---------------- scratch (device globals; no allocs) ----------------
__device__ float g_attn_part[32*4*1024];
__device__ float g_attn[32*1024];
__device__ float g_sumsq[2048];               // [0,1024)=q, [1024,2048)=k
__device__ float2 g_lnstat[B_*HW_];           // per-pixel {mean, rstd} of y-LN
__device__ __align__(16) __nv_bfloat16 g_ynT[(size_t)B_*PP_*C_];
__device__ __align__(16) __nv_bfloat16 g_xnT[(size_t)B_*HW_*C_];
__device__ __align__(16) __nv_bfloat16 g_avT[(size_t)B_*HW_*C_];
__device__ __align__(16) __nv_bfloat16 g_kvb[(size_t)B_*512*HW_];
__device__ __align__(16) __nv_bfloat16 g_qb[(size_t)B_*C_*HW_];
__device__ __align__(16) __nv_bfloat16 g_kb[(size_t)B_*C_*HW_];
__device__ __align__(16) __nv_bfloat16 g_vb[(size_t)B_*C_*HW_];
__device__ __align__(16) __nv_bfloat16 g_wq9[9*256*256];
__device__ __align__(16) __nv_bfloat16 g_wkv[512*256];
__device__ __align__(16) __nv_bfloat16 g_wproj[256*256];

// ================= portable tensor-core helpers (sm_80+ PTX) =================
__device__ __forceinline__ uint32_t smem_u32(const void* p) {
    uint32_t a;
    asm("{ .reg .u64 t; cvta.to.shared.u64 t, %1; cvt.u32.u64 %0, t; }" : "=r"(a) : "l"(p));
    return a;
}
__device__ __forceinline__ void cp16(uint32_t saddr, const void* g) {
    asm volatile("cp.async.cg.shared.global [%0], [%1], 16;" :: "r"(saddr), "l"(g));
}
#define CP_COMMIT() asm volatile("cp.async.commit_group;" ::: "memory")
#define CP_WAIT(n)  asm volatile("cp.async.wait_group %0;" :: "n"(n) : "memory")

__device__ __forceinline__ void ldm_x4(uint32_t* r, uint32_t a) {
    asm volatile("ldmatrix.sync.aligned.m8n8.x4.shared.b16 {%0,%1,%2,%3}, [%4];"
        : "=r"(r[0]), "=r"(r[1]), "=r"(r[2]), "=r"(r[3]) : "r"(a));
}
__device__ __forceinline__ void mma16816(float* c, const uint32_t* a, const uint32_t* b) {
    asm volatile("mma.sync.aligned.m16n8k16.row.col.f32.bf16.bf16.f32 "
        "{%0,%1,%2,%3}, {%4,%5,%6,%7}, {%8,%9}, {%0,%1,%2,%3};"
        : "+f"(c[0]), "+f"(c[1]), "+f"(c[2]), "+f"(c[3])
        : "r"(a[0]), "r"(a[1]), "r"(a[2]), "r"(a[3]), "r"(b[0]), "r"(b[1]));
}

// ---------------- K0: fused prologue (packs + zeros) ----------------
__global__ __launch_bounds__(256) void prep_kernel(
    const float* __restrict__ Wq, const float* __restrict__ Wkv, const float* __restrict__ Wproj)
{
    int id = blockIdx.x, tid = threadIdx.x;
    if (id < 2304) {
        int s = id >> 8, oc = id & 255;
        g_wq9[((size_t)s*256 + oc)*256 + tid] = __float2bfloat16(Wq[(size_t)oc*2304 + tid*9 + s]);
    } else if (id < 2816) {
        int i = (id - 2304)*256 + tid;
        g_wkv[i] = __float2bfloat16(Wkv[i]);
    } else if (id < 3072) {
        int i = (id - 2816)*256 + tid;
        g_wproj[i] = __float2bfloat16(Wproj[i]);
    } else if (id < 3080) {
        g_sumsq[(id - 3072)*256 + tid] = 0.f;
    } else {
        int j = id - 3080;
        int b = j / 516, i = j - b*516;
        if (tid < 64) {
            int py, px;
            if (i < 130)      { py = 0;   px = i; }
            else if (i < 260) { py = 129; px = i - 130; }
            else { int k = i - 260; py = 1 + (k >> 1); px = (k & 1) * 129; }
            size_t base = ((size_t)b*PP_ + (size_t)py*PW_ + px) * 256;
            ((uint2*)((char*)g_ynT + base*2))[tid] = make_uint2(0u, 0u);
        }
    }
}

// ---------------- K1: channel LayerNorm (stats saved, no fp32 yn) ----------------
__global__ __launch_bounds__(256) void layernorm_kernel(
    const float* __restrict__ x, const float* __restrict__ y,
    const float* __restrict__ wkv, const float* __restrict__ bkv,
    const float* __restrict__ wq,  const float* __restrict__ bq)
{
    __shared__ float tile[256*33];
    __shared__ float reds[8][32];
    __shared__ float reds2[8][32];
    __shared__ float swt[256], sbt[256];

    int tx = threadIdx.x, ty = threadIdx.y;
    int tid = ty*32 + tx;
    int p0 = blockIdx.x * 32;
    int b  = blockIdx.y;
    int which = blockIdx.z;

    const float* src  = which ? y   : x;
    const float* w    = which ? wq  : wkv;
    const float* bias = which ? bq  : bkv;

    swt[tid] = w[tid];
    sbt[tid] = bias[tid];

    float s = 0.f, s2 = 0.f;
    #pragma unroll 4
    for (int cc = 0; cc < 32; cc++) {
        int c = ty + cc*8;
        float v = src[(size_t)(b*C_ + c)*HW_ + p0 + tx];
        tile[c*33 + tx] = v;
        s += v; s2 += v*v;
    }
    reds[ty][tx] = s;
    reds2[ty][tx] = s2;
    __syncthreads();

    float m = 0.f, m2 = 0.f;
    #pragma unroll
    for (int j = 0; j < 8; j++) { m += reds[j][tx]; m2 += reds2[j][tx]; }
    float mean = m * (1.f/256.f);
    float var  = m2 * (1.f/256.f) - mean*mean;
    float rstd = rsqrtf(var + 1e-5f);

    if (which && ty == 0)
        g_lnstat[b*HW_ + p0 + tx] = make_float2(mean, rstd);

    #pragma unroll 4
    for (int cc = 0; cc < 32; cc++) {
        int c = ty + cc*8;
        float v = (tile[c*33 + tx] - mean) * rstd * swt[c] + sbt[c];
        tile[c*33 + tx] = v;
    }
    __syncthreads();

    int wpw = tid >> 5, ln = tid & 31;
    int yy  = p0 >> 7, x0c = p0 & 127;
    #pragma unroll
    for (int it = 0; it < 4; it++) {
        int pix = it*8 + wpw;
        size_t prow;
        char* dstT;
        if (which) {
            prow = (size_t)b*PP_ + (size_t)(yy+1)*PW_ + (x0c + pix + 1);
            dstT = (char*)g_ynT;
        } else {
            prow = (size_t)b*HW_ + p0 + pix;
            dstT = (char*)g_xnT;
        }
        uint4 o;
        uint32_t* po = &o.x;
        #pragma unroll
        for (int jj = 0; jj < 4; jj++) {
            float a  = tile[(ln*8 + jj*2    )*33 + pix];
            float bb = tile[(ln*8 + jj*2 + 1)*33 + pix];
            __nv_bfloat162 t = __floats2bfloat162_rn(a, bb);
            po[jj] = *(uint32_t*)&t;
        }
        *(uint4*)(dstT + prow*512 + ln*16) = o;
    }
}

// ---------------- K4: dense 3x3 conv via mma.sync bf16, 128oc x 128px, 2 CTA/SM ----------------
__global__ __launch_bounds__(256, 2) void conv3x3_mma_kernel()
{
    extern __shared__ char smem[];
    __shared__ float ssq[128];
    uint32_t sb = smem_u32(smem);
    const uint32_t sA0 = sb, sA1 = sb + 16384, sB = sb + 32768;

    int tid = threadIdx.x, lane = tid & 31, wid = tid >> 5;
    int xt  = blockIdx.x;
    int y0  = xt;
    int p0  = xt * 128;
    int oc0 = blockIdx.y * 128;
    int b   = blockIdx.z;
    int wm = wid >> 2, wn = wid & 3;

    if (tid < 128) ssq[tid] = 0.f;

    float acc[4][4][4];
    #pragma unroll
    for (int i = 0; i < 4; i++)
        #pragma unroll
        for (int j = 0; j < 4; j++)
            #pragma unroll
            for (int k = 0; k < 4; k++) acc[i][j][k] = 0.f;

    int buf = 0;
    for (int icc = 0; icc < 4; icc++) {
        int ic0 = icc * 64;

        for (int e = tid; e < 3120; e += 256) {
            int row = e >> 3, c = e & 7;
            int ry = row / 130, rx = row - ry*130;
            size_t pp = (size_t)b*PP_ + (size_t)(y0 + ry)*PW_ + rx;
            cp16(sB + row*128 + ((c ^ (row & 7)) << 4),
                 (const char*)g_ynT + pp*512 + ic0*2 + c*16);
        }
        {
            uint32_t dstb = buf ? sA1 : sA0;
            #pragma unroll
            for (int i = 0; i < 4; i++) {
                int e = tid + i*256;
                int row = e >> 3, c = e & 7;
                cp16(dstb + row*128 + ((c ^ (row & 7)) << 4),
                     (const char*)g_wq9 + (size_t)(0*256 + oc0 + row)*512 + ic0*2 + c*16);
            }
        }
        CP_COMMIT();

        for (int s = 0; s < 9; s++) {
            if (s < 8) {
                uint32_t dstb = (buf ^ 1) ? sA1 : sA0;
                #pragma unroll
                for (int i = 0; i < 4; i++) {
                    int e = tid + i*256;
                    int row = e >> 3, c = e & 7;
                    cp16(dstb + row*128 + ((c ^ (row & 7)) << 4),
                         (const char*)g_wq9 + (size_t)((s+1)*256 + oc0 + row)*512 + ic0*2 + c*16);
                }
                CP_COMMIT();
                CP_WAIT(1);
            } else {
                CP_WAIT(0);
            }
            __syncthreads();

            int dy = s / 3, dx = s - dy*3;
            uint32_t ab = buf ? sA1 : sA0;
            #pragma unroll
            for (int kk = 0; kk < 4; kk++) {
                uint32_t af[4][4], bfr[4][2];
                #pragma unroll
                for (int mi = 0; mi < 4; mi++) {
                    int row = wm*64 + mi*16 + (lane & 15);
                    int c = kk*2 + (lane >> 4);
                    ldm_x4(af[mi], ab + row*128 + ((c ^ (row & 7)) << 4));
                }
                #pragma unroll
                for (int ni = 0; ni < 4; ni += 2) {
                    int nio = ni + ((lane >> 4) & 1);
                    int n = wn*32 + nio*8 + (lane & 7);
                    int lr = dy*130 + n + dx;
                    int c = kk*2 + ((lane >> 3) & 1);
                    uint32_t tmp[4];
                    ldm_x4(tmp, sB + lr*128 + ((c ^ (lr & 7)) << 4));
                    bfr[ni][0] = tmp[0]; bfr[ni][1] = tmp[1];
                    bfr[ni+1][0] = tmp[2]; bfr[ni+1][1] = tmp[3];
                }
                #pragma unroll
                for (int mi = 0; mi < 4; mi++)
                    #pragma unroll
                    for (int ni = 0; ni < 4; ni++)
                        mma16816(acc[mi][ni], af[mi], bfr[ni]);
            }
            buf ^= 1;
            __syncthreads();
        }
    }

    #pragma unroll
    for (int mi = 0; mi < 4; mi++) {
        int oc = oc0 + wm*64 + mi*16 + (lane >> 2);
        float sa = 0.f, sbq = 0.f;
        #pragma unroll
        for (int ni = 0; ni < 4; ni++) {
            int px = p0 + wn*32 + ni*8 + (lane & 3)*2;
            float2 v0 = make_float2(acc[mi][ni][0], acc[mi][ni][1]);
            float2 v1 = make_float2(acc[mi][ni][2], acc[mi][ni][3]);
            __nv_bfloat162 t0 = __floats2bfloat162_rn(v0.x, v0.y);
            __nv_bfloat162 t1 = __floats2bfloat162_rn(v1.x, v1.y);
            *(__nv_bfloat162*)&g_qb[(size_t)(b*C_ + oc)*HW_ + px]     = t0;
            *(__nv_bfloat162*)&g_qb[(size_t)(b*C_ + oc + 8)*HW_ + px] = t1;
            sa  += v0.x*v0.x + v0.y*v0.y;
            sbq += v1.x*v1.x + v1.y*v1.y;
        }
        sa  += __shfl_xor_sync(0xffffffffu, sa, 1);
        sa  += __shfl_xor_sync(0xffffffffu, sa, 2);
        sbq += __shfl_xor_sync(0xffffffffu, sbq, 1);
        sbq += __shfl_xor_sync(0xffffffffu, sbq, 2);
        if ((lane & 3) == 0) {
            atomicAdd(&ssq[wm*64 + mi*16 + (lane >> 2)],     sa);
            atomicAdd(&ssq[wm*64 + mi*16 + (lane >> 2) + 8], sbq);
        }
    }
    __syncthreads();
    if (tid < 128) atomicAdd(&g_sumsq[b*256 + oc0 + tid], ssq[tid]);
}

// ---------------- K2/K9: 1x1 conv GEMMs via mma.sync bf16 ----------------
template<int MODE>
__global__ __launch_bounds__(256) void gemm1x1_mma_kernel(
    const float* __restrict__ Yin, const float* __restrict__ lnw,
    const float* __restrict__ lnb, float* __restrict__ ExtOut)
{
    extern __shared__ char smem[];
    __shared__ float2 s_stat[256];
    __shared__ float s_lnw[128], s_lnb[128];
    uint32_t sb = smem_u32(smem);
    const uint32_t sA[2] = {sb, sb + 16384};
    const uint32_t sB[2] = {sb + 32768, sb + 65536};

    const __nv_bfloat16* Wsrc = (MODE == 0) ? g_wkv : g_wproj;
    const __nv_bfloat16* Xsrc = (MODE == 0) ? g_xnT : g_avT;
    constexpr int OC = (MODE == 0) ? 512 : 256;

    int tid = threadIdx.x, lane = tid & 31, wid = tid >> 5;
    int p0  = blockIdx.x * 256;
    int oc0 = blockIdx.y * 128;
    int b   = blockIdx.z;
    int wm = wid >> 2, wn = wid & 3;

    if (MODE == 1) {
        s_stat[tid] = g_lnstat[b*HW_ + p0 + tid];
        if (tid < 128) { s_lnw[tid] = lnw[oc0 + tid]; s_lnb[tid] = lnb[oc0 + tid]; }
    }

    float acc[4][8][4];
    #pragma unroll
    for (int i = 0; i < 4; i++)
        #pragma unroll
        for (int j = 0; j < 8; j++)
            #pragma unroll
            for (int k = 0; k < 4; k++) acc[i][j][k] = 0.f;

    auto load_chunk = [&](int kc, int buf) {
        int ic0 = kc * 64;
        #pragma unroll
        for (int i = 0; i < 4; i++) {
            int e = tid + i*256;
            int row = e >> 3, c = e & 7;
            cp16(sA[buf] + row*128 + ((c ^ (row & 7)) << 4),
                 (const char*)Wsrc + (size_t)(oc0 + row)*512 + ic0*2 + c*16);
        }
        #pragma unroll
        for (int i = 0; i < 8; i++) {
            int e = tid + i*256;
            int row = e >> 3, c = e & 7;
            cp16(sB[buf] + row*128 + ((c ^ (row & 7)) << 4),
                 (const char*)Xsrc + ((size_t)b*HW_ + p0 + row)*512 + ic0*2 + c*16);
        }
        CP_COMMIT();
    };

    load_chunk(0, 0);
    int buf = 0;
    for (int kc = 0; kc < 4; kc++) {
        if (kc < 3) { load_chunk(kc + 1, buf ^ 1); CP_WAIT(1); }
        else        { CP_WAIT(0); }
        __syncthreads();

        #pragma unroll
        for (int kk = 0; kk < 4; kk++) {
            uint32_t af[4][4], bfr[8][2];
            #pragma unroll
            for (int mi = 0; mi < 4; mi++) {
                int row = wm*64 + mi*16 + (lane & 15);
                int c = kk*2 + (lane >> 4);
                ldm_x4(af[mi], sA[buf] + row*128 + ((c ^ (row & 7)) << 4));
            }
            #pragma unroll
            for (int ni = 0; ni < 8; ni += 2) {
                int nio = ni + ((lane >> 4) & 1);
                int row = wn*64 + nio*8 + (lane & 7);
                int c = kk*2 + ((lane >> 3) & 1);
                uint32_t tmp[4];
                ldm_x4(tmp, sB[buf] + row*128 + ((c ^ (row & 7)) << 4));
                bfr[ni][0] = tmp[0]; bfr[ni][1] = tmp[1];
                bfr[ni+1][0] = tmp[2]; bfr[ni+1][1] = tmp[3];
            }
            #pragma unroll
            for (int mi = 0; mi < 4; mi++)
                #pragma unroll
                for (int ni = 0; ni < 8; ni++)
                    mma16816(acc[mi][ni], af[mi], bfr[ni]);
        }
        buf ^= 1;
        __syncthreads();
    }

    #pragma unroll
    for (int mi = 0; mi < 4; mi++) {
        int oc = oc0 + wm*64 + mi*16 + (lane >> 2);
        int ocl = wm*64 + mi*16 + (lane >> 2);
        float wq0 = 0.f, bq0 = 0.f, wq1 = 0.f, bq1 = 0.f;
        if (MODE == 1) {
            wq0 = s_lnw[ocl]; bq0 = s_lnb[ocl];
            wq1 = s_lnw[ocl + 8]; bq1 = s_lnb[ocl + 8];
        }
        #pragma unroll
        for (int ni = 0; ni < 8; ni++) {
            int pxl = wn*64 + ni*8 + (lane & 3)*2;
            int px = p0 + pxl;
            float2 v0 = make_float2(acc[mi][ni][0], acc[mi][ni][1]);
            float2 v1 = make_float2(acc[mi][ni][2], acc[mi][ni][3]);
            if (MODE == 0) {
                __nv_bfloat162 t0 = __floats2bfloat162_rn(v0.x, v0.y);
                __nv_bfloat162 t1 = __floats2bfloat162_rn(v1.x, v1.y);
                *(__nv_bfloat162*)&g_kvb[(size_t)(b*OC + oc)*HW_ + px]     = t0;
                *(__nv_bfloat162*)&g_kvb[(size_t)(b*OC + oc + 8)*HW_ + px] = t1;
            } else {
                float2 sa  = s_stat[pxl];
                float2 sb2 = s_stat[pxl + 1];
                float2 y0 = *(const float2*)&Yin[(size_t)(b*C_ + oc)*HW_ + px];
                float2 y1 = *(const float2*)&Yin[(size_t)(b*C_ + oc + 8)*HW_ + px];
                v0.x += (y0.x - sa.x)*sa.y*wq0 + bq0;
                v0.y += (y0.y - sb2.x)*sb2.y*wq0 + bq0;
                v1.x += (y1.x - sa.x)*sa.y*wq1 + bq1;
                v1.y += (y1.y - sb2.x)*sb2.y*wq1 + bq1;
                *(float2*)&ExtOut[(size_t)(b*C_ + oc)*HW_ + px]     = v0;
                *(float2*)&ExtOut[(size_t)(b*C_ + oc + 8)*HW_ + px] = v1;
            }
        }
    }
}

// ---------------- K3: depthwise 3x3, 2 rows x 8 cols per thread, fused k sumsq ----------------
__global__ __launch_bounds__(256) void dwconv_kernel(const float* __restrict__ Wd)
{
    __shared__ float tile[34][132];
    __shared__ float redk[8];

    int tid = threadIdx.x;
    int lane = tid & 31, wid = tid >> 5;
    int r0 = blockIdx.x * 32;
    int z  = blockIdx.y;
    int ch = z & 511, b = z >> 9;

    float w[9];
    #pragma unroll
    for (int k = 0; k < 9; k++) w[k] = Wd[ch*9 + k];

    const __nv_bfloat16* in = g_kvb + (size_t)z*HW_;

    for (int r = wid; r < 34; r += 8) {
        int gy = r0 - 1 + r;
        int col = lane * 4;
        float f0 = 0.f, f1 = 0.f, f2 = 0.f, f3 = 0.f;
        if ((unsigned)gy < (unsigned)H_) {
            uint2 u = *(const uint2*)((const char*)in + gy*256 + col*2);
            __nv_bfloat162 q0 = *(__nv_bfloat162*)&u.x;
            __nv_bfloat162 q1 = *(__nv_bfloat162*)&u.y;
            f0 = __low2float(q0); f1 = __high2float(q0);
            f2 = __low2float(q1); f3 = __high2float(q1);
        }
        tile[r][1+col] = f0; tile[r][2+col] = f1;
        tile[r][3+col] = f2; tile[r][4+col] = f3;
        if (lane == 0) { tile[r][0] = 0.f; tile[r][129] = 0.f; }
    }
    __syncthreads();

    int row  = (tid >> 4) * 2;
    int col0 = (tid & 15) * 8;
    float o0[8], o1[8];
    #pragma unroll
    for (int j = 0; j < 8; j++) { o0[j] = 0.f; o1[j] = 0.f; }

    #pragma unroll
    for (int ky = 0; ky < 4; ky++) {
        const float* trow = &tile[row + ky][col0];
        float4 a  = *(const float4*)(trow);
        float4 b4 = *(const float4*)(trow + 4);
        float2 c2 = *(const float2*)(trow + 8);
        float v[10] = {a.x, a.y, a.z, a.w, b4.x, b4.y, b4.z, b4.w, c2.x, c2.y};
        if (ky < 3) {
            #pragma unroll
            for (int kx = 0; kx < 3; kx++)
                #pragma unroll
                for (int j = 0; j < 8; j++)
                    o0[j] += w[ky*3 + kx] * v[j + kx];
        }
        if (ky > 0) {
            #pragma unroll
            for (int kx = 0; kx < 3; kx++)
                #pragma unroll
                for (int j = 0; j < 8; j++)
                    o1[j] += w[(ky-1)*3 + kx] * v[j + kx];
        }
    }

    int gy0 = r0 + row;
    uint4 u0, u1;
    {
        __nv_bfloat162 t0 = __floats2bfloat162_rn(o0[0], o0[1]);
        __nv_bfloat162 t1 = __floats2bfloat162_rn(o0[2], o0[3]);
        __nv_bfloat162 t2 = __floats2bfloat162_rn(o0[4], o0[5]);
        __nv_bfloat162 t3 = __floats2bfloat162_rn(o0[6], o0[7]);
        u0.x = *(uint32_t*)&t0; u0.y = *(uint32_t*)&t1;
        u0.z = *(uint32_t*)&t2; u0.w = *(uint32_t*)&t3;
        __nv_bfloat162 s0 = __floats2bfloat162_rn(o1[0], o1[1]);
        __nv_bfloat162 s1 = __floats2bfloat162_rn(o1[2], o1[3]);
        __nv_bfloat162 s2 = __floats2bfloat162_rn(o1[4], o1[5]);
        __nv_bfloat162 s3 = __floats2bfloat162_rn(o1[6], o1[7]);
        u1.x = *(uint32_t*)&s0; u1.y = *(uint32_t*)&s1;
        u1.z = *(uint32_t*)&s2; u1.w = *(uint32_t*)&s3;
    }

    if (ch < 256) {
        __nv_bfloat16* dst = &g_kb[(size_t)(b*256 + ch)*HW_ + gy0*W_ + col0];
        *(uint4*)dst        = u0;
        *(uint4*)(dst + W_) = u1;
        float ss = 0.f;
        #pragma unroll
        for (int j = 0; j < 8; j++) ss += o0[j]*o0[j] + o1[j]*o1[j];
        #pragma unroll
        for (int off = 16; off > 0; off >>= 1) ss += __shfl_xor_sync(0xffffffffu, ss, off);
        if (lane == 0) redk[wid] = ss;
        __syncthreads();
        if (tid == 0) {
            float t = 0.f;
            #pragma unroll
            for (int j2 = 0; j2 < 8; j2++) t += redk[j2];
            atomicAdd(&g_sumsq[1024 + b*256 + ch], t);
        }
    } else {
        __nv_bfloat16* dst = &g_vb[(size_t)(b*256 + (ch - 256))*HW_ + gy0*W_ + col0];
        *(uint4*)dst        = u0;
        *(uint4*)(dst + W_) = u1;
    }
}

// ---------------- K6: q.kT via mma.sync bf16 ----------------
__global__ __launch_bounds__(256) void qk_mma_kernel()
{
    extern __shared__ char smem[];
    uint32_t sb = smem_u32(smem);
    float* part = (float*)(smem + 65536);

    int tid = threadIdx.x, lane = tid & 31, wid = tid >> 5;
    int bh = blockIdx.x, ns = blockIdx.y;
    int b = bh >> 3, h = bh & 7;

    const char* qbase = (const char*)(g_qb + (size_t)(b*C_ + h*32)*HW_ + ns*4096);
    const char* kbase = (const char*)(g_kb + (size_t)(b*C_ + h*32)*HW_ + ns*4096);

    float acc[2][4][4];
    #pragma unroll
    for (int i = 0; i < 2; i++)
        #pragma unroll
        for (int j = 0; j < 4; j++)
            #pragma unroll
            for (int k = 0; k < 4; k++) acc[i][j][k] = 0.f;

    auto load_tile = [&](int t, int buf) {
        uint32_t base = sb + buf*32768;
        #pragma unroll
        for (int i = 0; i < 4; i++) {
            int e = tid + i*256;
            int row = e >> 5, c = e & 31;
            cp16(base + row*512 + ((c ^ (row & 7)) << 4),
                 qbase + ((size_t)row*HW_ + t*256 + c*8)*2);
        }
        #pragma unroll
        for (int i = 0; i < 4; i++) {
            int e = tid + i*256;
            int row = e >> 5, c = e & 31;
            cp16(base + 16384 + row*512 + ((c ^ (row & 7)) << 4),
                 kbase + ((size_t)row*HW_ + t*256 + c*8)*2);
        }
        CP_COMMIT();
    };

    load_tile(0, 0);
    int buf = 0;
    for (int t = 0; t < 16; t++) {
        if (t < 15) { load_tile(t + 1, buf ^ 1); CP_WAIT(1); }
        else        { CP_WAIT(0); }
        __syncthreads();

        uint32_t qb = sb + buf*32768;
        uint32_t kb = qb + 16384;
        #pragma unroll
        for (int kw = 0; kw < 2; kw++) {
            int ks = wid*2 + kw;
            uint32_t af[2][4], bfr[4][2];
            #pragma unroll
            for (int mi = 0; mi < 2; mi++) {
                int row = mi*16 + (lane & 15);
                int c = ks*2 + (lane >> 4);
                ldm_x4(af[mi], qb + row*512 + ((c ^ (row & 7)) << 4));
            }
            #pragma unroll
            for (int ni = 0; ni < 4; ni += 2) {
                int nio = ni + ((lane >> 4) & 1);
                int row = nio*8 + (lane & 7);
                int c = ks*2 + ((lane >> 3) & 1);
                uint32_t tmp[4];
                ldm_x4(tmp, kb + row*512 + ((c ^ (row & 7)) << 4));
                bfr[ni][0] = tmp[0]; bfr[ni][1] = tmp[1];
                bfr[ni+1][0] = tmp[2]; bfr[ni+1][1] = tmp[3];
            }
            #pragma unroll
            for (int mi = 0; mi < 2; mi++)
                #pragma unroll
                for (int ni = 0; ni < 4; ni++)
                    mma16816(acc[mi][ni], af[mi], bfr[ni]);
        }
        buf ^= 1;
        __syncthreads();
    }

    float* my = part + wid*1024;
    #pragma unroll
    for (int mi = 0; mi < 2; mi++)
        #pragma unroll
        for (int ni = 0; ni < 4; ni++)
            #pragma unroll
            for (int r = 0; r < 4; r++) {
                int row = mi*16 + (lane >> 2) + ((r >> 1) & 1)*8;
                int col = ni*8 + (lane & 3)*2 + (r & 1);
                my[row*32 + col] = acc[mi][ni][r];
            }
    __syncthreads();
    #pragma unroll
    for (int e = tid; e < 1024; e += 256) {
        float s = 0.f;
        #pragma unroll
        for (int wv = 0; wv < 8; wv++) s += part[wv*1024 + e];
        g_attn_part[(size_t)(bh*4 + ns)*1024 + e] = s;
    }
}

// ---------------- K7: softmax (inlines norm finalize) ----------------
__global__ __launch_bounds__(1024) void softmax_kernel(const float* __restrict__ temp)
{
    int bh = blockIdx.x;
    int b = bh >> 3, h = bh & 7;
    int tid = threadIdx.x;
    int c = tid >> 5, d = tid & 31;

    float s = 0.f;
    #pragma unroll
    for (int ns = 0; ns < 4; ns++)
        s += g_attn_part[(size_t)(bh*4 + ns)*1024 + c*32 + d];

    float iq = 1.f / fmaxf(sqrtf(g_sumsq[b*256 + h*32 + c]), 1e-12f);
    float ik = 1.f / fmaxf(sqrtf(g_sumsq[1024 + b*256 + h*32 + d]), 1e-12f);
    float val = s * iq * ik * temp[h];

    float m = val;
    #pragma unroll
    for (int o = 16; o > 0; o >>= 1) m = fmaxf(m, __shfl_xor_sync(0xffffffffu, m, o));
    float e = expf(val - m);
    float sum = e;
    #pragma unroll
    for (int o = 16; o > 0; o >>= 1) sum += __shfl_xor_sync(0xffffffffu, sum, o);

    g_attn[bh*1024 + c*32 + d] = e / sum;
}

// ---------------- K8: avT = (attn @ v)^T, bf16 ----------------
__global__ __launch_bounds__(256) void av_kernel()
{
    __shared__ float sA[1024];
    int tid = threadIdx.x;
    int bh  = blockIdx.y;
    int n0  = blockIdx.x * 256;
    int b = bh >> 3, h = bh & 7;

    #pragma unroll
    for (int e = tid; e < 1024; e += 256) sA[e] = g_attn[bh*1024 + e];
    __syncthreads();

    const __nv_bfloat16* vbase = g_vb + (size_t)(b*256 + h*32)*HW_ + n0 + tid;
    float acc[32];
    #pragma unroll
    for (int cc = 0; cc < 32; cc++) acc[cc] = 0.f;

    #pragma unroll
    for (int d4 = 0; d4 < 32; d4 += 4) {
        float v0 = __bfloat162float(vbase[(size_t)(d4+0)*HW_]);
        float v1 = __bfloat162float(vbase[(size_t)(d4+1)*HW_]);
        float v2 = __bfloat162float(vbase[(size_t)(d4+2)*HW_]);
        float v3 = __bfloat162float(vbase[(size_t)(d4+3)*HW_]);
        #pragma unroll
        for (int cc = 0; cc < 32; cc++) {
            float4 a = *(const float4*)&sA[cc*32 + d4];
            acc[cc] += a.x*v0 + a.y*v1 + a.z*v2 + a.w*v3;
        }
    }
    size_t p = (size_t)b*HW_ + n0 + tid;
    uint32_t* obase = (uint32_t*)((char*)g_avT + p*512 + h*64);
    #pragma unroll
    for (int cc = 0; cc < 16; cc++) {
        __nv_bfloat162 t = __floats2bfloat162_rn(acc[cc*2], acc[cc*2+1]);
        obase[cc] = *(uint32_t*)&t;
    }
}

// ---------------- launch: gemm0 serial; dwconv concurrent with conv3x3 ----------------
extern "C" void kernel_launch(void* const* d_in, const int* in_sizes, int n_in,
                              void* d_out, int out_size)
{
    const float* x       = (const float*)d_in[0];
    const float* y       = (const float*)d_in[1];
    const float* ln_kv_w = (const float*)d_in[2];
    const float* ln_kv_b = (const float*)d_in[3];
    const float* ln_q_w  = (const float*)d_in[4];
    const float* ln_q_b  = (const float*)d_in[5];
    const float* W_kv    = (const float*)d_in[6];
    const float* W_dw    = (const float*)d_in[7];
    const float* W_q     = (const float*)d_in[8];
    const float* W_proj  = (const float*)d_in[9];
    const float* temp    = (const float*)d_in[10];
    float* out = (float*)d_out;

    cudaFuncSetAttribute(conv3x3_mma_kernel, cudaFuncAttributeMaxDynamicSharedMemorySize, 82688);
    cudaFuncSetAttribute(gemm1x1_mma_kernel<0>, cudaFuncAttributeMaxDynamicSharedMemorySize, 98304);
    cudaFuncSetAttribute(gemm1x1_mma_kernel<1>, cudaFuncAttributeMaxDynamicSharedMemorySize, 98304);
    cudaFuncSetAttribute(qk_mma_kernel, cudaFuncAttributeMaxDynamicSharedMemorySize, 98304);

    cudaStream_t s2;
    cudaEvent_t e1, e2;
    cudaStreamCreateWithFlags(&s2, cudaStreamNonBlocking);
    cudaEventCreateWithFlags(&e1, cudaEventDisableTiming);
    cudaEventCreateWithFlags(&e2, cudaEventDisableTiming);

    prep_kernel<<<5144, 256>>>(W_q, W_kv, W_proj);
    layernorm_kernel<<<dim3(HW_/32, B_, 2), dim3(32, 8)>>>(x, y, ln_kv_w, ln_kv_b, ln_q_w, ln_q_b);

    // gemm0 runs serially (can't co-reside with conv anyway)
    gemm1x1_mma_kernel<0><<<dim3(HW_/256, 4, B_), 256, 98304>>>(nullptr, nullptr, nullptr, nullptr);

    // fork: dwconv (18KB smem — fits beside conv's 2x82.7KB) on side stream
    cudaEventRecord(e1, 0);
    cudaStreamWaitEvent(s2, e1, 0);
    dwconv_kernel<<<dim3(H_/32, B_*512), 256, 0, s2>>>(W_dw);
    cudaEventRecord(e2, s2);

    conv3x3_mma_kernel<<<dim3(128, 2, B_), 256, 82688>>>();

    // join
    cudaStreamWaitEvent(0, e2, 0);
    qk_mma_kernel<<<dim3(32, 4), 256, 98304>>>();
    softmax_kernel<<<32, 1024>>>(temp);
    av_kernel<<<dim3(HW_/256, 32), 256>>>();
    gemm1x1_mma_kernel<1><<<dim3(HW_/256, 2, B_), 256, 98304>>>(y, ln_q_w, ln_q_b, out);

    cudaEventDestroy(e1);
    cudaEventDestroy(e2);
    cudaStreamDestroy(s2);
}

// round 14
// speedup vs baseline: 1.1085x; 1.1085x over previous
#include <cuda_runtime.h>
#include <cuda_bf16.h>
#include <cstdint>

#define B_ 4
#define C_ 256
#define H_ 128
#define W_ 128
#define HW_ (H_*W_)
#define HEADS_ 8
#define PW_ 130
#define PP_ (PW_*PW_)

// ---------------- scratch (device globals; no allocs) ----------------
__device__ float g_attn_part[32*4*1024];
__device__ float g_attn[32*1024];
__device__ float g_sumsq[2048];               // [0,1024)=q, [1024,2048)=k
__device__ float2 g_lnstat[B_*HW_];           // per-pixel {mean, rstd} of y-LN
__device__ __align__(16) __nv_bfloat16 g_ynT[(size_t)B_*PP_*C_];
__device__ __align__(16) __nv_bfloat16 g_xnT[(size_t)B_*HW_*C_];
__device__ __align__(16) __nv_bfloat16 g_avT[(size_t)B_*HW_*C_];
__device__ __align__(16) __nv_bfloat16 g_kvb[(size_t)B_*512*HW_];
__device__ __align__(16) __nv_bfloat16 g_qb[(size_t)B_*C_*HW_];
__device__ __align__(16) __nv_bfloat16 g_kb[(size_t)B_*C_*HW_];
__device__ __align__(16) __nv_bfloat16 g_vb[(size_t)B_*C_*HW_];
__device__ __align__(16) __nv_bfloat16 g_wq9[9*256*256];
__device__ __align__(16) __nv_bfloat16 g_wkv[512*256];
__device__ __align__(16) __nv_bfloat16 g_wproj[256*256];

// ================= portable tensor-core helpers (sm_80+ PTX) =================
__device__ __forceinline__ uint32_t smem_u32(const void* p) {
    uint32_t a;
    asm("{ .reg .u64 t; cvta.to.shared.u64 t, %1; cvt.u32.u64 %0, t; }" : "=r"(a) : "l"(p));
    return a;
}
__device__ __forceinline__ void cp16(uint32_t saddr, const void* g) {
    asm volatile("cp.async.cg.shared.global [%0], [%1], 16;" :: "r"(saddr), "l"(g));
}
#define CP_COMMIT() asm volatile("cp.async.commit_group;" ::: "memory")
#define CP_WAIT(n)  asm volatile("cp.async.wait_group %0;" :: "n"(n) : "memory")

__device__ __forceinline__ void ldm_x4(uint32_t* r, uint32_t a) {
    asm volatile("ldmatrix.sync.aligned.m8n8.x4.shared.b16 {%0,%1,%2,%3}, [%4];"
        : "=r"(r[0]), "=r"(r[1]), "=r"(r[2]), "=r"(r[3]) : "r"(a));
}
__device__ __forceinline__ void mma16816(float* c, const uint32_t* a, const uint32_t* b) {
    asm volatile("mma.sync.aligned.m16n8k16.row.col.f32.bf16.bf16.f32 "
        "{%0,%1,%2,%3}, {%4,%5,%6,%7}, {%8,%9}, {%0,%1,%2,%3};"
        : "+f"(c[0]), "+f"(c[1]), "+f"(c[2]), "+f"(c[3])
        : "r"(a[0]), "r"(a[1]), "r"(a[2]), "r"(a[3]), "r"(b[0]), "r"(b[1]));
}

// ---------------- K0: fused prologue (packs + zeros) ----------------
__global__ __launch_bounds__(256) void prep_kernel(
    const float* __restrict__ Wq, const float* __restrict__ Wkv, const float* __restrict__ Wproj)
{
    int id = blockIdx.x, tid = threadIdx.x;
    if (id < 2304) {
        int s = id >> 8, oc = id & 255;
        g_wq9[((size_t)s*256 + oc)*256 + tid] = __float2bfloat16(Wq[(size_t)oc*2304 + tid*9 + s]);
    } else if (id < 2816) {
        int i = (id - 2304)*256 + tid;
        g_wkv[i] = __float2bfloat16(Wkv[i]);
    } else if (id < 3072) {
        int i = (id - 2816)*256 + tid;
        g_wproj[i] = __float2bfloat16(Wproj[i]);
    } else if (id < 3080) {
        g_sumsq[(id - 3072)*256 + tid] = 0.f;
    } else {
        int j = id - 3080;
        int b = j / 516, i = j - b*516;
        if (tid < 64) {
            int py, px;
            if (i < 130)      { py = 0;   px = i; }
            else if (i < 260) { py = 129; px = i - 130; }
            else { int k = i - 260; py = 1 + (k >> 1); px = (k & 1) * 129; }
            size_t base = ((size_t)b*PP_ + (size_t)py*PW_ + px) * 256;
            ((uint2*)((char*)g_ynT + base*2))[tid] = make_uint2(0u, 0u);
        }
    }
}

// ---------------- K1: channel LayerNorm (split by which; stats saved, no fp32 yn) ----------------
__global__ __launch_bounds__(256) void layernorm_kernel(
    const float* __restrict__ src, const float* __restrict__ w,
    const float* __restrict__ bias, int which)
{
    __shared__ float tile[256*33];
    __shared__ float reds[8][32];
    __shared__ float reds2[8][32];
    __shared__ float swt[256], sbt[256];

    int tx = threadIdx.x, ty = threadIdx.y;
    int tid = ty*32 + tx;
    int p0 = blockIdx.x * 32;
    int b  = blockIdx.y;

    swt[tid] = w[tid];
    sbt[tid] = bias[tid];

    float s = 0.f, s2 = 0.f;
    #pragma unroll 4
    for (int cc = 0; cc < 32; cc++) {
        int c = ty + cc*8;
        float v = src[(size_t)(b*C_ + c)*HW_ + p0 + tx];
        tile[c*33 + tx] = v;
        s += v; s2 += v*v;
    }
    reds[ty][tx] = s;
    reds2[ty][tx] = s2;
    __syncthreads();

    float m = 0.f, m2 = 0.f;
    #pragma unroll
    for (int j = 0; j < 8; j++) { m += reds[j][tx]; m2 += reds2[j][tx]; }
    float mean = m * (1.f/256.f);
    float var  = m2 * (1.f/256.f) - mean*mean;
    float rstd = rsqrtf(var + 1e-5f);

    if (which && ty == 0)
        g_lnstat[b*HW_ + p0 + tx] = make_float2(mean, rstd);

    #pragma unroll 4
    for (int cc = 0; cc < 32; cc++) {
        int c = ty + cc*8;
        float v = (tile[c*33 + tx] - mean) * rstd * swt[c] + sbt[c];
        tile[c*33 + tx] = v;
    }
    __syncthreads();

    int wpw = tid >> 5, ln = tid & 31;
    int yy  = p0 >> 7, x0c = p0 & 127;
    #pragma unroll
    for (int it = 0; it < 4; it++) {
        int pix = it*8 + wpw;
        size_t prow;
        char* dstT;
        if (which) {
            prow = (size_t)b*PP_ + (size_t)(yy+1)*PW_ + (x0c + pix + 1);
            dstT = (char*)g_ynT;
        } else {
            prow = (size_t)b*HW_ + p0 + pix;
            dstT = (char*)g_xnT;
        }
        uint4 o;
        uint32_t* po = &o.x;
        #pragma unroll
        for (int jj = 0; jj < 4; jj++) {
            float a  = tile[(ln*8 + jj*2    )*33 + pix];
            float bb = tile[(ln*8 + jj*2 + 1)*33 + pix];
            __nv_bfloat162 t = __floats2bfloat162_rn(a, bb);
            po[jj] = *(uint32_t*)&t;
        }
        *(uint4*)(dstT + prow*512 + ln*16) = o;
    }
}

// ---------------- K4: dense 3x3 conv via mma.sync bf16, 128oc x 128px, 2 CTA/SM ----------------
__global__ __launch_bounds__(256, 2) void conv3x3_mma_kernel()
{
    extern __shared__ char smem[];
    __shared__ float ssq[128];
    uint32_t sb = smem_u32(smem);
    const uint32_t sA0 = sb, sA1 = sb + 16384, sB = sb + 32768;

    int tid = threadIdx.x, lane = tid & 31, wid = tid >> 5;
    int xt  = blockIdx.x;
    int y0  = xt;
    int p0  = xt * 128;
    int oc0 = blockIdx.y * 128;
    int b   = blockIdx.z;
    int wm = wid >> 2, wn = wid & 3;

    if (tid < 128) ssq[tid] = 0.f;

    float acc[4][4][4];
    #pragma unroll
    for (int i = 0; i < 4; i++)
        #pragma unroll
        for (int j = 0; j < 4; j++)
            #pragma unroll
            for (int k = 0; k < 4; k++) acc[i][j][k] = 0.f;

    int buf = 0;
    for (int icc = 0; icc < 4; icc++) {
        int ic0 = icc * 64;

        for (int e = tid; e < 3120; e += 256) {
            int row = e >> 3, c = e & 7;
            int ry = row / 130, rx = row - ry*130;
            size_t pp = (size_t)b*PP_ + (size_t)(y0 + ry)*PW_ + rx;
            cp16(sB + row*128 + ((c ^ (row & 7)) << 4),
                 (const char*)g_ynT + pp*512 + ic0*2 + c*16);
        }
        {
            uint32_t dstb = buf ? sA1 : sA0;
            #pragma unroll
            for (int i = 0; i < 4; i++) {
                int e = tid + i*256;
                int row = e >> 3, c = e & 7;
                cp16(dstb + row*128 + ((c ^ (row & 7)) << 4),
                     (const char*)g_wq9 + (size_t)(0*256 + oc0 + row)*512 + ic0*2 + c*16);
            }
        }
        CP_COMMIT();

        for (int s = 0; s < 9; s++) {
            if (s < 8) {
                uint32_t dstb = (buf ^ 1) ? sA1 : sA0;
                #pragma unroll
                for (int i = 0; i < 4; i++) {
                    int e = tid + i*256;
                    int row = e >> 3, c = e & 7;
                    cp16(dstb + row*128 + ((c ^ (row & 7)) << 4),
                         (const char*)g_wq9 + (size_t)((s+1)*256 + oc0 + row)*512 + ic0*2 + c*16);
                }
                CP_COMMIT();
                CP_WAIT(1);
            } else {
                CP_WAIT(0);
            }
            __syncthreads();

            int dy = s / 3, dx = s - dy*3;
            uint32_t ab = buf ? sA1 : sA0;
            #pragma unroll
            for (int kk = 0; kk < 4; kk++) {
                uint32_t af[4][4], bfr[4][2];
                #pragma unroll
                for (int mi = 0; mi < 4; mi++) {
                    int row = wm*64 + mi*16 + (lane & 15);
                    int c = kk*2 + (lane >> 4);
                    ldm_x4(af[mi], ab + row*128 + ((c ^ (row & 7)) << 4));
                }
                #pragma unroll
                for (int ni = 0; ni < 4; ni += 2) {
                    int nio = ni + ((lane >> 4) & 1);
                    int n = wn*32 + nio*8 + (lane & 7);
                    int lr = dy*130 + n + dx;
                    int c = kk*2 + ((lane >> 3) & 1);
                    uint32_t tmp[4];
                    ldm_x4(tmp, sB + lr*128 + ((c ^ (lr & 7)) << 4));
                    bfr[ni][0] = tmp[0]; bfr[ni][1] = tmp[1];
                    bfr[ni+1][0] = tmp[2]; bfr[ni+1][1] = tmp[3];
                }
                #pragma unroll
                for (int mi = 0; mi < 4; mi++)
                    #pragma unroll
                    for (int ni = 0; ni < 4; ni++)
                        mma16816(acc[mi][ni], af[mi], bfr[ni]);
            }
            buf ^= 1;
            __syncthreads();
        }
    }

    #pragma unroll
    for (int mi = 0; mi < 4; mi++) {
        int oc = oc0 + wm*64 + mi*16 + (lane >> 2);
        float sa = 0.f, sbq = 0.f;
        #pragma unroll
        for (int ni = 0; ni < 4; ni++) {
            int px = p0 + wn*32 + ni*8 + (lane & 3)*2;
            float2 v0 = make_float2(acc[mi][ni][0], acc[mi][ni][1]);
            float2 v1 = make_float2(acc[mi][ni][2], acc[mi][ni][3]);
            __nv_bfloat162 t0 = __floats2bfloat162_rn(v0.x, v0.y);
            __nv_bfloat162 t1 = __floats2bfloat162_rn(v1.x, v1.y);
            *(__nv_bfloat162*)&g_qb[(size_t)(b*C_ + oc)*HW_ + px]     = t0;
            *(__nv_bfloat162*)&g_qb[(size_t)(b*C_ + oc + 8)*HW_ + px] = t1;
            sa  += v0.x*v0.x + v0.y*v0.y;
            sbq += v1.x*v1.x + v1.y*v1.y;
        }
        sa  += __shfl_xor_sync(0xffffffffu, sa, 1);
        sa  += __shfl_xor_sync(0xffffffffu, sa, 2);
        sbq += __shfl_xor_sync(0xffffffffu, sbq, 1);
        sbq += __shfl_xor_sync(0xffffffffu, sbq, 2);
        if ((lane & 3) == 0) {
            atomicAdd(&ssq[wm*64 + mi*16 + (lane >> 2)],     sa);
            atomicAdd(&ssq[wm*64 + mi*16 + (lane >> 2) + 8], sbq);
        }
    }
    __syncthreads();
    if (tid < 128) atomicAdd(&g_sumsq[b*256 + oc0 + tid], ssq[tid]);
}

// ---------------- K2/K9: 1x1 conv GEMMs via mma.sync bf16 ----------------
template<int MODE>
__global__ __launch_bounds__(256) void gemm1x1_mma_kernel(
    const float* __restrict__ Yin, const float* __restrict__ lnw,
    const float* __restrict__ lnb, float* __restrict__ ExtOut)
{
    extern __shared__ char smem[];
    __shared__ float2 s_stat[256];
    __shared__ float s_lnw[128], s_lnb[128];
    uint32_t sb = smem_u32(smem);
    const uint32_t sA[2] = {sb, sb + 16384};
    const uint32_t sB[2] = {sb + 32768, sb + 65536};

    const __nv_bfloat16* Wsrc = (MODE == 0) ? g_wkv : g_wproj;
    const __nv_bfloat16* Xsrc = (MODE == 0) ? g_xnT : g_avT;
    constexpr int OC = (MODE == 0) ? 512 : 256;

    int tid = threadIdx.x, lane = tid & 31, wid = tid >> 5;
    int p0  = blockIdx.x * 256;
    int oc0 = blockIdx.y * 128;
    int b   = blockIdx.z;
    int wm = wid >> 2, wn = wid & 3;

    if (MODE == 1) {
        s_stat[tid] = g_lnstat[b*HW_ + p0 + tid];
        if (tid < 128) { s_lnw[tid] = lnw[oc0 + tid]; s_lnb[tid] = lnb[oc0 + tid]; }
    }

    float acc[4][8][4];
    #pragma unroll
    for (int i = 0; i < 4; i++)
        #pragma unroll
        for (int j = 0; j < 8; j++)
            #pragma unroll
            for (int k = 0; k < 4; k++) acc[i][j][k] = 0.f;

    auto load_chunk = [&](int kc, int buf) {
        int ic0 = kc * 64;
        #pragma unroll
        for (int i = 0; i < 4; i++) {
            int e = tid + i*256;
            int row = e >> 3, c = e & 7;
            cp16(sA[buf] + row*128 + ((c ^ (row & 7)) << 4),
                 (const char*)Wsrc + (size_t)(oc0 + row)*512 + ic0*2 + c*16);
        }
        #pragma unroll
        for (int i = 0; i < 8; i++) {
            int e = tid + i*256;
            int row = e >> 3, c = e & 7;
            cp16(sB[buf] + row*128 + ((c ^ (row & 7)) << 4),
                 (const char*)Xsrc + ((size_t)b*HW_ + p0 + row)*512 + ic0*2 + c*16);
        }
        CP_COMMIT();
    };

    load_chunk(0, 0);
    int buf = 0;
    for (int kc = 0; kc < 4; kc++) {
        if (kc < 3) { load_chunk(kc + 1, buf ^ 1); CP_WAIT(1); }
        else        { CP_WAIT(0); }
        __syncthreads();

        #pragma unroll
        for (int kk = 0; kk < 4; kk++) {
            uint32_t af[4][4], bfr[8][2];
            #pragma unroll
            for (int mi = 0; mi < 4; mi++) {
                int row = wm*64 + mi*16 + (lane & 15);
                int c = kk*2 + (lane >> 4);
                ldm_x4(af[mi], sA[buf] + row*128 + ((c ^ (row & 7)) << 4));
            }
            #pragma unroll
            for (int ni = 0; ni < 8; ni += 2) {
                int nio = ni + ((lane >> 4) & 1);
                int row = wn*64 + nio*8 + (lane & 7);
                int c = kk*2 + ((lane >> 3) & 1);
                uint32_t tmp[4];
                ldm_x4(tmp, sB[buf] + row*128 + ((c ^ (row & 7)) << 4));
                bfr[ni][0] = tmp[0]; bfr[ni][1] = tmp[1];
                bfr[ni+1][0] = tmp[2]; bfr[ni+1][1] = tmp[3];
            }
            #pragma unroll
            for (int mi = 0; mi < 4; mi++)
                #pragma unroll
                for (int ni = 0; ni < 8; ni++)
                    mma16816(acc[mi][ni], af[mi], bfr[ni]);
        }
        buf ^= 1;
        __syncthreads();
    }

    #pragma unroll
    for (int mi = 0; mi < 4; mi++) {
        int oc = oc0 + wm*64 + mi*16 + (lane >> 2);
        int ocl = wm*64 + mi*16 + (lane >> 2);
        float wq0 = 0.f, bq0 = 0.f, wq1 = 0.f, bq1 = 0.f;
        if (MODE == 1) {
            wq0 = s_lnw[ocl]; bq0 = s_lnb[ocl];
            wq1 = s_lnw[ocl + 8]; bq1 = s_lnb[ocl + 8];
        }
        #pragma unroll
        for (int ni = 0; ni < 8; ni++) {
            int pxl = wn*64 + ni*8 + (lane & 3)*2;
            int px = p0 + pxl;
            float2 v0 = make_float2(acc[mi][ni][0], acc[mi][ni][1]);
            float2 v1 = make_float2(acc[mi][ni][2], acc[mi][ni][3]);
            if (MODE == 0) {
                __nv_bfloat162 t0 = __floats2bfloat162_rn(v0.x, v0.y);
                __nv_bfloat162 t1 = __floats2bfloat162_rn(v1.x, v1.y);
                *(__nv_bfloat162*)&g_kvb[(size_t)(b*OC + oc)*HW_ + px]     = t0;
                *(__nv_bfloat162*)&g_kvb[(size_t)(b*OC + oc + 8)*HW_ + px] = t1;
            } else {
                float2 sa  = s_stat[pxl];
                float2 sb2 = s_stat[pxl + 1];
                float2 y0 = *(const float2*)&Yin[(size_t)(b*C_ + oc)*HW_ + px];
                float2 y1 = *(const float2*)&Yin[(size_t)(b*C_ + oc + 8)*HW_ + px];
                v0.x += (y0.x - sa.x)*sa.y*wq0 + bq0;
                v0.y += (y0.y - sb2.x)*sb2.y*wq0 + bq0;
                v1.x += (y1.x - sa.x)*sa.y*wq1 + bq1;
                v1.y += (y1.y - sb2.x)*sb2.y*wq1 + bq1;
                *(float2*)&ExtOut[(size_t)(b*C_ + oc)*HW_ + px]     = v0;
                *(float2*)&ExtOut[(size_t)(b*C_ + oc + 8)*HW_ + px] = v1;
            }
        }
    }
}

// ---------------- K3: depthwise 3x3, 2 rows x 8 cols per thread, fused k sumsq ----------------
__global__ __launch_bounds__(256) void dwconv_kernel(const float* __restrict__ Wd)
{
    __shared__ float tile[34][132];
    __shared__ float redk[8];

    int tid = threadIdx.x;
    int lane = tid & 31, wid = tid >> 5;
    int r0 = blockIdx.x * 32;
    int z  = blockIdx.y;
    int ch = z & 511, b = z >> 9;

    float w[9];
    #pragma unroll
    for (int k = 0; k < 9; k++) w[k] = Wd[ch*9 + k];

    const __nv_bfloat16* in = g_kvb + (size_t)z*HW_;

    for (int r = wid; r < 34; r += 8) {
        int gy = r0 - 1 + r;
        int col = lane * 4;
        float f0 = 0.f, f1 = 0.f, f2 = 0.f, f3 = 0.f;
        if ((unsigned)gy < (unsigned)H_) {
            uint2 u = *(const uint2*)((const char*)in + gy*256 + col*2);
            __nv_bfloat162 q0 = *(__nv_bfloat162*)&u.x;
            __nv_bfloat162 q1 = *(__nv_bfloat162*)&u.y;
            f0 = __low2float(q0); f1 = __high2float(q0);
            f2 = __low2float(q1); f3 = __high2float(q1);
        }
        tile[r][1+col] = f0; tile[r][2+col] = f1;
        tile[r][3+col] = f2; tile[r][4+col] = f3;
        if (lane == 0) { tile[r][0] = 0.f; tile[r][129] = 0.f; }
    }
    __syncthreads();

    int row  = (tid >> 4) * 2;
    int col0 = (tid & 15) * 8;
    float o0[8], o1[8];
    #pragma unroll
    for (int j = 0; j < 8; j++) { o0[j] = 0.f; o1[j] = 0.f; }

    #pragma unroll
    for (int ky = 0; ky < 4; ky++) {
        const float* trow = &tile[row + ky][col0];
        float4 a  = *(const float4*)(trow);
        float4 b4 = *(const float4*)(trow + 4);
        float2 c2 = *(const float2*)(trow + 8);
        float v[10] = {a.x, a.y, a.z, a.w, b4.x, b4.y, b4.z, b4.w, c2.x, c2.y};
        if (ky < 3) {
            #pragma unroll
            for (int kx = 0; kx < 3; kx++)
                #pragma unroll
                for (int j = 0; j < 8; j++)
                    o0[j] += w[ky*3 + kx] * v[j + kx];
        }
        if (ky > 0) {
            #pragma unroll
            for (int kx = 0; kx < 3; kx++)
                #pragma unroll
                for (int j = 0; j < 8; j++)
                    o1[j] += w[(ky-1)*3 + kx] * v[j + kx];
        }
    }

    int gy0 = r0 + row;
    uint4 u0, u1;
    {
        __nv_bfloat162 t0 = __floats2bfloat162_rn(o0[0], o0[1]);
        __nv_bfloat162 t1 = __floats2bfloat162_rn(o0[2], o0[3]);
        __nv_bfloat162 t2 = __floats2bfloat162_rn(o0[4], o0[5]);
        __nv_bfloat162 t3 = __floats2bfloat162_rn(o0[6], o0[7]);
        u0.x = *(uint32_t*)&t0; u0.y = *(uint32_t*)&t1;
        u0.z = *(uint32_t*)&t2; u0.w = *(uint32_t*)&t3;
        __nv_bfloat162 s0 = __floats2bfloat162_rn(o1[0], o1[1]);
        __nv_bfloat162 s1 = __floats2bfloat162_rn(o1[2], o1[3]);
        __nv_bfloat162 s2 = __floats2bfloat162_rn(o1[4], o1[5]);
        __nv_bfloat162 s3 = __floats2bfloat162_rn(o1[6], o1[7]);
        u1.x = *(uint32_t*)&s0; u1.y = *(uint32_t*)&s1;
        u1.z = *(uint32_t*)&s2; u1.w = *(uint32_t*)&s3;
    }

    if (ch < 256) {
        __nv_bfloat16* dst = &g_kb[(size_t)(b*256 + ch)*HW_ + gy0*W_ + col0];
        *(uint4*)dst        = u0;
        *(uint4*)(dst + W_) = u1;
        float ss = 0.f;
        #pragma unroll
        for (int j = 0; j < 8; j++) ss += o0[j]*o0[j] + o1[j]*o1[j];
        #pragma unroll
        for (int off = 16; off > 0; off >>= 1) ss += __shfl_xor_sync(0xffffffffu, ss, off);
        if (lane == 0) redk[wid] = ss;
        __syncthreads();
        if (tid == 0) {
            float t = 0.f;
            #pragma unroll
            for (int j2 = 0; j2 < 8; j2++) t += redk[j2];
            atomicAdd(&g_sumsq[1024 + b*256 + ch], t);
        }
    } else {
        __nv_bfloat16* dst = &g_vb[(size_t)(b*256 + (ch - 256))*HW_ + gy0*W_ + col0];
        *(uint4*)dst        = u0;
        *(uint4*)(dst + W_) = u1;
    }
}

// ---------------- K6: q.kT via mma.sync bf16 ----------------
__global__ __launch_bounds__(256) void qk_mma_kernel()
{
    extern __shared__ char smem[];
    uint32_t sb = smem_u32(smem);
    float* part = (float*)(smem + 65536);

    int tid = threadIdx.x, lane = tid & 31, wid = tid >> 5;
    int bh = blockIdx.x, ns = blockIdx.y;
    int b = bh >> 3, h = bh & 7;

    const char* qbase = (const char*)(g_qb + (size_t)(b*C_ + h*32)*HW_ + ns*4096);
    const char* kbase = (const char*)(g_kb + (size_t)(b*C_ + h*32)*HW_ + ns*4096);

    float acc[2][4][4];
    #pragma unroll
    for (int i = 0; i < 2; i++)
        #pragma unroll
        for (int j = 0; j < 4; j++)
            #pragma unroll
            for (int k = 0; k < 4; k++) acc[i][j][k] = 0.f;

    auto load_tile = [&](int t, int buf) {
        uint32_t base = sb + buf*32768;
        #pragma unroll
        for (int i = 0; i < 4; i++) {
            int e = tid + i*256;
            int row = e >> 5, c = e & 31;
            cp16(base + row*512 + ((c ^ (row & 7)) << 4),
                 qbase + ((size_t)row*HW_ + t*256 + c*8)*2);
        }
        #pragma unroll
        for (int i = 0; i < 4; i++) {
            int e = tid + i*256;
            int row = e >> 5, c = e & 31;
            cp16(base + 16384 + row*512 + ((c ^ (row & 7)) << 4),
                 kbase + ((size_t)row*HW_ + t*256 + c*8)*2);
        }
        CP_COMMIT();
    };

    load_tile(0, 0);
    int buf = 0;
    for (int t = 0; t < 16; t++) {
        if (t < 15) { load_tile(t + 1, buf ^ 1); CP_WAIT(1); }
        else        { CP_WAIT(0); }
        __syncthreads();

        uint32_t qb = sb + buf*32768;
        uint32_t kb = qb + 16384;
        #pragma unroll
        for (int kw = 0; kw < 2; kw++) {
            int ks = wid*2 + kw;
            uint32_t af[2][4], bfr[4][2];
            #pragma unroll
            for (int mi = 0; mi < 2; mi++) {
                int row = mi*16 + (lane & 15);
                int c = ks*2 + (lane >> 4);
                ldm_x4(af[mi], qb + row*512 + ((c ^ (row & 7)) << 4));
            }
            #pragma unroll
            for (int ni = 0; ni < 4; ni += 2) {
                int nio = ni + ((lane >> 4) & 1);
                int row = nio*8 + (lane & 7);
                int c = ks*2 + ((lane >> 3) & 1);
                uint32_t tmp[4];
                ldm_x4(tmp, kb + row*512 + ((c ^ (row & 7)) << 4));
                bfr[ni][0] = tmp[0]; bfr[ni][1] = tmp[1];
                bfr[ni+1][0] = tmp[2]; bfr[ni+1][1] = tmp[3];
            }
            #pragma unroll
            for (int mi = 0; mi < 2; mi++)
                #pragma unroll
                for (int ni = 0; ni < 4; ni++)
                    mma16816(acc[mi][ni], af[mi], bfr[ni]);
        }
        buf ^= 1;
        __syncthreads();
    }

    float* my = part + wid*1024;
    #pragma unroll
    for (int mi = 0; mi < 2; mi++)
        #pragma unroll
        for (int ni = 0; ni < 4; ni++)
            #pragma unroll
            for (int r = 0; r < 4; r++) {
                int row = mi*16 + (lane >> 2) + ((r >> 1) & 1)*8;
                int col = ni*8 + (lane & 3)*2 + (r & 1);
                my[row*32 + col] = acc[mi][ni][r];
            }
    __syncthreads();
    #pragma unroll
    for (int e = tid; e < 1024; e += 256) {
        float s = 0.f;
        #pragma unroll
        for (int wv = 0; wv < 8; wv++) s += part[wv*1024 + e];
        g_attn_part[(size_t)(bh*4 + ns)*1024 + e] = s;
    }
}

// ---------------- K7: softmax (inlines norm finalize) ----------------
__global__ __launch_bounds__(1024) void softmax_kernel(const float* __restrict__ temp)
{
    int bh = blockIdx.x;
    int b = bh >> 3, h = bh & 7;
    int tid = threadIdx.x;
    int c = tid >> 5, d = tid & 31;

    float s = 0.f;
    #pragma unroll
    for (int ns = 0; ns < 4; ns++)
        s += g_attn_part[(size_t)(bh*4 + ns)*1024 + c*32 + d];

    float iq = 1.f / fmaxf(sqrtf(g_sumsq[b*256 + h*32 + c]), 1e-12f);
    float ik = 1.f / fmaxf(sqrtf(g_sumsq[1024 + b*256 + h*32 + d]), 1e-12f);
    float val = s * iq * ik * temp[h];

    float m = val;
    #pragma unroll
    for (int o = 16; o > 0; o >>= 1) m = fmaxf(m, __shfl_xor_sync(0xffffffffu, m, o));
    float e = expf(val - m);
    float sum = e;
    #pragma unroll
    for (int o = 16; o > 0; o >>= 1) sum += __shfl_xor_sync(0xffffffffu, sum, o);

    g_attn[bh*1024 + c*32 + d] = e / sum;
}

// ---------------- K8: avT = (attn @ v)^T, bf16 ----------------
__global__ __launch_bounds__(256) void av_kernel()
{
    __shared__ float sA[1024];
    int tid = threadIdx.x;
    int bh  = blockIdx.y;
    int n0  = blockIdx.x * 256;
    int b = bh >> 3, h = bh & 7;

    #pragma unroll
    for (int e = tid; e < 1024; e += 256) sA[e] = g_attn[bh*1024 + e];
    __syncthreads();

    const __nv_bfloat16* vbase = g_vb + (size_t)(b*256 + h*32)*HW_ + n0 + tid;
    float acc[32];
    #pragma unroll
    for (int cc = 0; cc < 32; cc++) acc[cc] = 0.f;

    #pragma unroll
    for (int d4 = 0; d4 < 32; d4 += 4) {
        float v0 = __bfloat162float(vbase[(size_t)(d4+0)*HW_]);
        float v1 = __bfloat162float(vbase[(size_t)(d4+1)*HW_]);
        float v2 = __bfloat162float(vbase[(size_t)(d4+2)*HW_]);
        float v3 = __bfloat162float(vbase[(size_t)(d4+3)*HW_]);
        #pragma unroll
        for (int cc = 0; cc < 32; cc++) {
            float4 a = *(const float4*)&sA[cc*32 + d4];
            acc[cc] += a.x*v0 + a.y*v1 + a.z*v2 + a.w*v3;
        }
    }
    size_t p = (size_t)b*HW_ + n0 + tid;
    uint32_t* obase = (uint32_t*)((char*)g_avT + p*512 + h*64);
    #pragma unroll
    for (int cc = 0; cc < 16; cc++) {
        __nv_bfloat162 t = __floats2bfloat162_rn(acc[cc*2], acc[cc*2+1]);
        obase[cc] = *(uint32_t*)&t;
    }
}

// ---------------- launch: two independent front chains, round-12-style fork ----------------
extern "C" void kernel_launch(void* const* d_in, const int* in_sizes, int n_in,
                              void* d_out, int out_size)
{
    const float* x       = (const float*)d_in[0];
    const float* y       = (const float*)d_in[1];
    const float* ln_kv_w = (const float*)d_in[2];
    const float* ln_kv_b = (const float*)d_in[3];
    const float* ln_q_w  = (const float*)d_in[4];
    const float* ln_q_b  = (const float*)d_in[5];
    const float* W_kv    = (const float*)d_in[6];
    const float* W_dw    = (const float*)d_in[7];
    const float* W_q     = (const float*)d_in[8];
    const float* W_proj  = (const float*)d_in[9];
    const float* temp    = (const float*)d_in[10];
    float* out = (float*)d_out;

    cudaFuncSetAttribute(conv3x3_mma_kernel, cudaFuncAttributeMaxDynamicSharedMemorySize, 82688);
    cudaFuncSetAttribute(gemm1x1_mma_kernel<0>, cudaFuncAttributeMaxDynamicSharedMemorySize, 98304);
    cudaFuncSetAttribute(gemm1x1_mma_kernel<1>, cudaFuncAttributeMaxDynamicSharedMemorySize, 98304);
    cudaFuncSetAttribute(qk_mma_kernel, cudaFuncAttributeMaxDynamicSharedMemorySize, 98304);

    cudaStream_t s2;
    cudaEvent_t e1, e2;
    cudaStreamCreateWithFlags(&s2, cudaStreamNonBlocking);
    cudaEventCreateWithFlags(&e1, cudaEventDisableTiming);
    cudaEventCreateWithFlags(&e2, cudaEventDisableTiming);

    // s2 chain: LNx starts immediately (independent of prep)
    layernorm_kernel<<<dim3(HW_/32, B_), dim3(32, 8), 0, s2>>>(x, ln_kv_w, ln_kv_b, 0);

    // s1 chain: prep -> LNy -> conv
    prep_kernel<<<5144, 256>>>(W_q, W_kv, W_proj);
    cudaEventRecord(e1, 0);                    // prep done (wkv/wproj/sumsq ready)
    layernorm_kernel<<<dim3(HW_/32, B_), dim3(32, 8)>>>(y, ln_q_w, ln_q_b, 1);

    // s2: wait for prep (wkv + sumsq zero), then gemm0 -> dwconv
    cudaStreamWaitEvent(s2, e1, 0);
    gemm1x1_mma_kernel<0><<<dim3(HW_/256, 4, B_), 256, 98304, s2>>>(nullptr, nullptr, nullptr, nullptr);
    dwconv_kernel<<<dim3(H_/32, B_*512), 256, 0, s2>>>(W_dw);
    cudaEventRecord(e2, s2);

    // s1: conv (needs ynT from LNy + wq9/borders/sumsq from prep — same stream)
    conv3x3_mma_kernel<<<dim3(128, 2, B_), 256, 82688>>>();

    // join: qk/av need both chains
    cudaStreamWaitEvent(0, e2, 0);
    qk_mma_kernel<<<dim3(32, 4), 256, 98304>>>();
    softmax_kernel<<<32, 1024>>>(temp);
    av_kernel<<<dim3(HW_/256, 32), 256>>>();
    gemm1x1_mma_kernel<1><<<dim3(HW_/256, 2, B_), 256, 98304>>>(y, ln_q_w, ln_q_b, out);

    cudaEventDestroy(e1);
    cudaEventDestroy(e2);
    cudaStreamDestroy(s2);
}